// round 13
// baseline (speedup 1.0000x reference)
#include <cuda_runtime.h>

#define NN 4
#define HH 480
#define WW 640
#define W4 (WW / 4)
// padded CHW-f4 plane: rows -2..HH+1, f4-cols -1..W4 ; origin offset (2,1)
#define PR (HH + 4)
#define PC (W4 + 2)
#define PS (PR * PC)

// Scratch (static device arrays; zero-initialized -> padded borders stay 0)
__device__ float4 g_t1p[NN * 4 * PS];    // padded CHW-f4 ping
__device__ float4 g_t2p[NN * 4 * PS];    // padded CHW-f4 pong
__device__ float4 g_th [NN * HH * WW];   // theta NHWC f4
__device__ float4 g_xt [NN * HH * WW];   // x packed NHWC (c=0..2, lane w = 0)

typedef unsigned long long u64;

__device__ __forceinline__ u64 pk(float lo, float hi) {
    u64 r; asm("mov.b64 %0, {%1,%2};" : "=l"(r) : "f"(lo), "f"(hi)); return r;
}
__device__ __forceinline__ void upk(u64 v, float& lo, float& hi) {
    asm("mov.b64 {%0,%1}, %2;" : "=f"(lo), "=f"(hi) : "l"(v));
}
__device__ __forceinline__ u64 fma2(u64 a, u64 b, u64 c) {
    u64 d; asm("fma.rn.f32x2 %0, %1, %2, %3;" : "=l"(d) : "l"(a), "l"(b), "l"(c));
    return d;
}

// ---------------------------------------------------------------------------
// Kernel 0: pack x [N,3,H,W] -> NHWC float4 (4th lane zero)
// ---------------------------------------------------------------------------
__global__ void __launch_bounds__(256) pack_x_kernel(const float* __restrict__ x) {
    int idx = blockIdx.x * 256 + threadIdx.x;
    const int total = NN * HH * WW;
    if (idx >= total) return;
    int n  = idx / (HH * WW);
    int hw = idx - n * (HH * WW);
    const float* xb = x + (size_t)n * 3 * HH * WW + hw;
    float4 v;
    v.x = __ldg(&xb[0]);
    v.y = __ldg(&xb[HH * WW]);
    v.z = __ldg(&xb[2 * HH * WW]);
    v.w = 0.f;
    g_xt[idx] = v;
}

// ---------------------------------------------------------------------------
// 5x5 conv, pad 2, OC=4. Block 32x4 = 128 thr; thread computes 4 ADJACENT px
// on TWO ADJACENT rows (yA = y0+2ty, yA+1). The 6 shared input rows are read
// once each (3 LDS.128 + dup); output A uses taps ky=r (fresh LDS), output B
// uses taps ky=r-1 reused from registers (wprev). FFMA2 packed over oc.
// SRC: 0 = external x (bounds-checked), 1 = g_t1p, 2 = g_t2p (unconditional
// padded loads). NHWC_OUT -> theta f4 into g_th, else padded CHW DST.
// NOTE: output batch stride is 4*PS (OC=4 planes) regardless of IC.
// ---------------------------------------------------------------------------
template <int IC, int SRC, int DST, bool NHWC_OUT>
__global__ void __launch_bounds__(128) conv5_kernel(
    const float* __restrict__ xin, const float* __restrict__ w,
    const float* __restrict__ b)
{
    __shared__ float      tile[IC][12][136];
    __shared__ ulonglong2 wsh2[IC][5][5];   // [ic][ky][kx] -> (pk(w0,w1), pk(w2,w3))
    __shared__ float4     b4s;

    const int tx  = threadIdx.x;
    const int ty  = threadIdx.y;            // 0..3
    const int tid = ty * 32 + tx;           // 0..127
    const int x0  = blockIdx.x * 128;
    const int y0  = blockIdx.y * 8;
    const int n   = blockIdx.z;

    // weights: src layout [OC=4][IC][5][5]
    if (tid < IC * 25) {
        int ic = tid / 25;
        int k  = tid - ic * 25;        // ky*5+kx
        float w0 = __ldg(&w[(0 * IC + ic) * 25 + k]);
        float w1 = __ldg(&w[(1 * IC + ic) * 25 + k]);
        float w2 = __ldg(&w[(2 * IC + ic) * 25 + k]);
        float w3 = __ldg(&w[(3 * IC + ic) * 25 + k]);
        wsh2[ic][k / 5][k % 5] = make_ulonglong2(pk(w0, w1), pk(w2, w3));
    }
    if (tid == 0)
        b4s = make_float4(__ldg(&b[0]), __ldg(&b[1]), __ldg(&b[2]), __ldg(&b[3]));

    // prologue: tile rows y0-2..y0+9, f4-cols x0/4-1 .. x0/4+32
    {
        const int cbase = (x0 >> 2) - 1;
        if (SRC == 0) {
            const float4* in4 = reinterpret_cast<const float4*>(xin + (size_t)n * IC * HH * WW);
#pragma unroll 1
            for (int i = tid; i < IC * 12 * 34; i += 128) {
                int ic  = i / (12 * 34);
                int rem = i - ic * (12 * 34);
                int r   = rem / 34;
                int c4  = rem - r * 34;
                int gy  = y0 + r - 2;
                int gx4 = cbase + c4;
                float4 v = make_float4(0.f, 0.f, 0.f, 0.f);
                if ((unsigned)gy < (unsigned)HH && (unsigned)gx4 < (unsigned)W4)
                    v = __ldg(&in4[((size_t)ic * HH + gy) * W4 + gx4]);
                *reinterpret_cast<float4*>(&tile[ic][r][4 * c4]) = v;
            }
        } else {
            const float4* in4 = ((SRC == 1) ? g_t1p : g_t2p) + (size_t)n * 4 * PS;
#pragma unroll 1
            for (int i = tid; i < IC * 12 * 34; i += 128) {
                int ic  = i / (12 * 34);
                int rem = i - ic * (12 * 34);
                int r   = rem / 34;
                int c4  = rem - r * 34;
                // padded, unconditional: row y0+r-2 -> padded row y0+r; col +1
                float4 v = __ldg(&in4[(size_t)ic * PS + (y0 + r) * PC + (cbase + c4 + 1)]);
                *reinterpret_cast<float4*>(&tile[ic][r][4 * c4]) = v;
            }
        }
    }
    __syncthreads();

    // acc pairs per row: [p] = pixel, 01 = (oc0,oc1), 23 = (oc2,oc3)
    u64 accA01[4], accA23[4], accB01[4], accB23[4];
    {
        const u64 b01 = pk(b4s.x, b4s.y);
        const u64 b23 = pk(b4s.z, b4s.w);
#pragma unroll
        for (int p = 0; p < 4; ++p) {
            accA01[p] = b01; accA23[p] = b23;
            accB01[p] = b01; accB23[p] = b23;
        }
    }

#pragma unroll 1
    for (int ic = 0; ic < IC; ++ic) {
        ulonglong2 wprev[5];
#pragma unroll
        for (int r = 0; r < 6; ++r) {
            const float4* rowp =
                reinterpret_cast<const float4*>(&tile[ic][2 * ty + r][4 * tx]);
            const float4 a0 = rowp[0];
            const float4 a1 = rowp[1];
            const float4 a2 = rowp[2];
            const float v[12] = {a0.x, a0.y, a0.z, a0.w,
                                 a1.x, a1.y, a1.z, a1.w,
                                 a2.x, a2.y, a2.z, a2.w};
            u64 d[8];
#pragma unroll
            for (int j = 0; j < 8; ++j) d[j] = pk(v[2 + j], v[2 + j]);
#pragma unroll
            for (int kx = 0; kx < 5; ++kx) {
                if (r >= 1) {   // output B (row yA+1), taps ky = r-1 from regs
                    const ulonglong2 wp = wprev[kx];
#pragma unroll
                    for (int p = 0; p < 4; ++p) {
                        accB01[p] = fma2(d[p + kx], wp.x, accB01[p]);
                        accB23[p] = fma2(d[p + kx], wp.y, accB23[p]);
                    }
                }
                if (r < 5) {    // output A (row yA), taps ky = r fresh
                    const ulonglong2 wc = wsh2[ic][r][kx];
#pragma unroll
                    for (int p = 0; p < 4; ++p) {
                        accA01[p] = fma2(d[p + kx], wc.x, accA01[p]);
                        accA23[p] = fma2(d[p + kx], wc.y, accA23[p]);
                    }
                    wprev[kx] = wc;
                }
            }
        }
    }

    const int yA = y0 + 2 * ty;
    const int xb = x0 + 4 * tx;

    float oA[4][4], oB[4][4];   // [oc][px]
#pragma unroll
    for (int p = 0; p < 4; ++p) {
        upk(accA01[p], oA[0][p], oA[1][p]);
        upk(accA23[p], oA[2][p], oA[3][p]);
        upk(accB01[p], oB[0][p], oB[1][p]);
        upk(accB23[p], oB[2][p], oB[3][p]);
    }

    if (NHWC_OUT) {
        float4* oA4 = g_th + (size_t)n * HH * WW + yA * WW + xb;
        float4* oB4 = oA4 + WW;
#pragma unroll
        for (int p = 0; p < 4; ++p) {
            oA4[p] = make_float4(oA[0][p], oA[1][p], oA[2][p], oA[3][p]);
            oB4[p] = make_float4(oB[0][p], oB[1][p], oB[2][p], oB[3][p]);
        }
    } else {
        // OC = 4 planes always -> batch stride 4*PS
        float4* outp = ((DST == 1) ? g_t1p : g_t2p) + (size_t)n * 4 * PS;
        const int fx = (x0 >> 2) + tx + 1;
#pragma unroll
        for (int oc = 0; oc < 4; ++oc) {
            float4* pl = outp + (size_t)oc * PS + (yA + 2) * PC + fx;
            pl[0]  = make_float4(oA[oc][0], oA[oc][1], oA[oc][2], oA[oc][3]);
            pl[PC] = make_float4(oB[oc][0], oB[oc][1], oB[oc][2], oB[oc][3]);
        }
    }
}

// ---------------------------------------------------------------------------
// Fused: grid build + bilinear grid_sample + stride-3 3x3 conv epilogue.
// theta in NHWC float4 (g_th). x in NHWC float4 (g_xt). Corner cache: the 9
// subsamples perturb the sample point by <<1 px -> refetch only on index change.
// ---------------------------------------------------------------------------
__device__ __forceinline__ float4 fetch4(const float4* __restrict__ b, int x, int y) {
    if ((unsigned)x < (unsigned)WW && (unsigned)y < (unsigned)HH)
        return __ldg(&b[y * WW + x]);
    return make_float4(0.f, 0.f, 0.f, 0.f);
}

__global__ void __launch_bounds__(256) stn_sample_kernel(
    const float* __restrict__ wr, const float* __restrict__ br,
    float* __restrict__ out)
{
    __shared__ float wsh[81];
    __shared__ float bsh[3];
    __shared__ float so[3][32][9];

    const int tx  = threadIdx.x;
    const int ty  = threadIdx.y;
    const int tid = ty * 32 + tx;
    if (tid < 81) wsh[tid] = __ldg(&wr[tid]);
    if (tid < 3)  bsh[tid] = __ldg(&br[tid]);
    __syncthreads();

    const int h0 = blockIdx.x * 32;
    const int w0 = blockIdx.y * 8;
    const int n  = blockIdx.z;
    const int h  = h0 + tx;
    const int w  = w0 + ty;

    const float4* tb = g_th + (size_t)n * HH * WW;
    const float4* xb = g_xt + (size_t)n * HH * WW;

    const float4 th = __ldg(&tb[h * WW + w]);

    const float yy = -1.f + 2.f * (float)h / (float)(HH - 1);
    const float xx = -1.f + 2.f * (float)w / (float)(WW - 1);

    float acc0 = 0.f, acc1 = 0.f, acc2 = 0.f;

    int cxi = (int)0x80000000, cyi = (int)0x80000000;
    float4 c00, c10, c01, c11;
    c00 = c10 = c01 = c11 = make_float4(0.f, 0.f, 0.f, 0.f);

#pragma unroll
    for (int i = 0; i < 3; ++i) {
        const float lyv = (float)(i - 1) * (3.0f / (float)HH);
#pragma unroll
        for (int j = 0; j < 3; ++j) {
            const float lxv = (float)(j - 1) * (3.0f / (float)WW);
            const float gx = yy + th.x * lyv + th.y * lxv;   // grid[...,0] (x coord)
            const float gy = xx + th.z * lyv + th.w * lxv;   // grid[...,1] (y coord)
            const float ix = ((gx + 1.0f) * (float)WW - 1.0f) * 0.5f;
            const float iy = ((gy + 1.0f) * (float)HH - 1.0f) * 0.5f;
            const float ix0 = floorf(ix);
            const float iy0 = floorf(iy);
            const float wx1 = ix - ix0;
            const float wy1 = iy - iy0;
            const float wx0 = 1.0f - wx1;
            const float wy0 = 1.0f - wy1;
            const int xi = (int)ix0;
            const int yi = (int)iy0;

            if (xi != cxi || yi != cyi) {
                c00 = fetch4(xb, xi,     yi);
                c10 = fetch4(xb, xi + 1, yi);
                c01 = fetch4(xb, xi,     yi + 1);
                c11 = fetch4(xb, xi + 1, yi + 1);
                cxi = xi; cyi = yi;
            }

            const float w00 = wx0 * wy0, w10 = wx1 * wy0;
            const float w01 = wx0 * wy1, w11 = wx1 * wy1;

            const float vx = c00.x * w00 + c10.x * w10 + c01.x * w01 + c11.x * w11;
            const float vy = c00.y * w00 + c10.y * w10 + c01.y * w01 + c11.y * w11;
            const float vz = c00.z * w00 + c10.z * w10 + c01.z * w01 + c11.z * w11;

            const int k = i * 3 + j;
            acc0 += wsh[0 * 27 + k] * vx + wsh[0 * 27 + 9 + k] * vy + wsh[0 * 27 + 18 + k] * vz;
            acc1 += wsh[1 * 27 + k] * vx + wsh[1 * 27 + 9 + k] * vy + wsh[1 * 27 + 18 + k] * vz;
            acc2 += wsh[2 * 27 + k] * vx + wsh[2 * 27 + 9 + k] * vy + wsh[2 * 27 + 18 + k] * vz;
        }
    }

    so[0][tx][ty] = acc0 + bsh[0];
    so[1][tx][ty] = acc1 + bsh[1];
    so[2][tx][ty] = acc2 + bsh[2];
    __syncthreads();

    for (int e = tid; e < 3 * 32 * 8; e += 256) {
        int oc = e >> 8;
        int r  = (e >> 3) & 31;
        int c  = e & 7;
        out[((size_t)(n * 3 + oc) * HH + h0 + r) * WW + w0 + c] = so[oc][r][c];
    }
}

// ---------------------------------------------------------------------------
extern "C" void kernel_launch(void* const* d_in, const int* in_sizes, int n_in,
                              void* d_out, int out_size)
{
    const float* x  = (const float*)d_in[0];
    const float* w1 = (const float*)d_in[1];
    const float* b1 = (const float*)d_in[2];
    const float* w2 = (const float*)d_in[3];
    const float* b2 = (const float*)d_in[4];
    const float* w3 = (const float*)d_in[5];
    const float* b3 = (const float*)d_in[6];
    const float* w4 = (const float*)d_in[7];
    const float* b4 = (const float*)d_in[8];
    const float* wr = (const float*)d_in[9];
    const float* br = (const float*)d_in[10];
    float* out = (float*)d_out;

    const dim3 cb(32, 4);
    const dim3 cg(WW / 128, HH / 8, NN);     // (5, 60, 4)

    pack_x_kernel<<<(NN * HH * WW + 255) / 256, 256>>>(x);

    conv5_kernel<3, 0, 1, false><<<cg, cb>>>(x, w1, b1);        // x    -> t1p
    conv5_kernel<4, 1, 2, false><<<cg, cb>>>(nullptr, w2, b2);  // t1p  -> t2p
    conv5_kernel<4, 2, 1, false><<<cg, cb>>>(nullptr, w3, b3);  // t2p  -> t1p
    conv5_kernel<4, 1, 2, true ><<<cg, cb>>>(nullptr, w4, b4);  // t1p  -> g_th

    const dim3 sb(32, 8);
    const dim3 sg(HH / 32, WW / 8, NN);      // (15, 80, 4)
    stn_sample_kernel<<<sg, sb>>>(wr, br, out);
}

// round 15
// speedup vs baseline: 1.0689x; 1.0689x over previous
#include <cuda_runtime.h>

#define NN 4
#define HH 480
#define WW 640
#define W4 (WW / 4)
// padded CHW-f4 plane: rows -2..HH+1, f4-cols -1..W4 ; origin offset (2,1)
#define PR (HH + 4)
#define PC (W4 + 2)
#define PS (PR * PC)

// Scratch (static device arrays; zero-initialized -> padded borders stay 0)
__device__ float4 g_t1p[NN * 4 * PS];    // padded CHW-f4 ping
__device__ float4 g_t2p[NN * 4 * PS];    // padded CHW-f4 pong
__device__ float4 g_th [NN * HH * WW];   // theta NHWC f4
__device__ float4 g_xt [NN * HH * WW];   // x packed NHWC (c=0..2, lane w = 0)

typedef unsigned long long u64;

__device__ __forceinline__ u64 pk(float lo, float hi) {
    u64 r; asm("mov.b64 %0, {%1,%2};" : "=l"(r) : "f"(lo), "f"(hi)); return r;
}
__device__ __forceinline__ void upk(u64 v, float& lo, float& hi) {
    asm("mov.b64 {%0,%1}, %2;" : "=f"(lo), "=f"(hi) : "l"(v));
}
__device__ __forceinline__ u64 fma2(u64 a, u64 b, u64 c) {
    u64 d; asm("fma.rn.f32x2 %0, %1, %2, %3;" : "=l"(d) : "l"(a), "l"(b), "l"(c));
    return d;
}

// ---------------------------------------------------------------------------
// 5x5 conv, pad 2, OC=4. Block 32x8 = 256 thr; thread computes 4 ADJACENT px
// on ONE row (R10 structure: best measured operating point).
// FFMA2 packed over oc: acc u64 pairs (oc0,oc1)/(oc2,oc3); weights ulonglong2.
// SRC: 0 = external x (bounds-checked, + fused g_xt pack), 1/2 = padded bufs
// (unconditional loads). NHWC_OUT -> theta f4 into g_th, else padded CHW DST.
// Output batch stride always 4*PS (OC=4).
// ---------------------------------------------------------------------------
template <int IC, int SRC, int DST, bool NHWC_OUT>
__global__ void __launch_bounds__(256) conv5_kernel(
    const float* __restrict__ xin, const float* __restrict__ w,
    const float* __restrict__ b)
{
    __shared__ float      tile[IC][12][136];
    __shared__ ulonglong2 wsh2[IC][5][5];   // [ic][ky][kx] -> (pk(w0,w1), pk(w2,w3))
    __shared__ float4     b4s;

    const int tx  = threadIdx.x;
    const int ty  = threadIdx.y;
    const int tid = ty * 32 + tx;
    const int x0  = blockIdx.x * 128;
    const int y0  = blockIdx.y * 8;
    const int n   = blockIdx.z;

    // weights: src layout [OC=4][IC][5][5]
    if (tid < IC * 25) {
        int ic = tid / 25;
        int k  = tid - ic * 25;        // ky*5+kx
        float w0 = __ldg(&w[(0 * IC + ic) * 25 + k]);
        float w1 = __ldg(&w[(1 * IC + ic) * 25 + k]);
        float w2 = __ldg(&w[(2 * IC + ic) * 25 + k]);
        float w3 = __ldg(&w[(3 * IC + ic) * 25 + k]);
        wsh2[ic][k / 5][k % 5] = make_ulonglong2(pk(w0, w1), pk(w2, w3));
    }
    if (tid == 0)
        b4s = make_float4(__ldg(&b[0]), __ldg(&b[1]), __ldg(&b[2]), __ldg(&b[3]));

    // prologue: tile rows y0-2..y0+9, f4-cols x0/4-1 .. x0/4+32
    {
        const int cbase = (x0 >> 2) - 1;
        if (SRC == 0) {
            const float4* in4 = reinterpret_cast<const float4*>(xin + (size_t)n * IC * HH * WW);
#pragma unroll 1
            for (int i = tid; i < IC * 12 * 34; i += 256) {
                int ic  = i / (12 * 34);
                int rem = i - ic * (12 * 34);
                int r   = rem / 34;
                int c4  = rem - r * 34;
                int gy  = y0 + r - 2;
                int gx4 = cbase + c4;
                float4 v = make_float4(0.f, 0.f, 0.f, 0.f);
                if ((unsigned)gy < (unsigned)HH && (unsigned)gx4 < (unsigned)W4)
                    v = __ldg(&in4[((size_t)ic * HH + gy) * W4 + gx4]);
                *reinterpret_cast<float4*>(&tile[ic][r][4 * c4]) = v;
            }
        } else {
            const float4* in4 = ((SRC == 1) ? g_t1p : g_t2p) + (size_t)n * 4 * PS;
#pragma unroll 1
            for (int i = tid; i < IC * 12 * 34; i += 256) {
                int ic  = i / (12 * 34);
                int rem = i - ic * (12 * 34);
                int r   = rem / 34;
                int c4  = rem - r * 34;
                // padded, unconditional: logical row y0+r-2 -> padded row y0+r; col +1
                float4 v = __ldg(&in4[(size_t)ic * PS + (y0 + r) * PC + (cbase + c4 + 1)]);
                *reinterpret_cast<float4*>(&tile[ic][r][4 * c4]) = v;
            }
        }
    }
    __syncthreads();

    const int y  = y0 + ty;
    const int xb = x0 + 4 * tx;

    // Fused NHWC pack of x (conv1 only): tile cols 4tx+4..4tx+7 = px xb..xb+3
    if (SRC == 0) {
        const float4 c0 = *reinterpret_cast<const float4*>(&tile[0][ty + 2][4 * tx + 4]);
        const float4 c1 = *reinterpret_cast<const float4*>(&tile[1][ty + 2][4 * tx + 4]);
        const float4 c2 = *reinterpret_cast<const float4*>(&tile[2][ty + 2][4 * tx + 4]);
        float4* xp = g_xt + (size_t)n * HH * WW + y * WW + xb;
        xp[0] = make_float4(c0.x, c1.x, c2.x, 0.f);
        xp[1] = make_float4(c0.y, c1.y, c2.y, 0.f);
        xp[2] = make_float4(c0.z, c1.z, c2.z, 0.f);
        xp[3] = make_float4(c0.w, c1.w, c2.w, 0.f);
    }

    // acc pairs: acc01[p] = (oc0,oc1), acc23[p] = (oc2,oc3) for pixel p
    u64 acc01[4], acc23[4];
    {
        const u64 b01 = pk(b4s.x, b4s.y);
        const u64 b23 = pk(b4s.z, b4s.w);
#pragma unroll
        for (int p = 0; p < 4; ++p) { acc01[p] = b01; acc23[p] = b23; }
    }

#pragma unroll 1
    for (int ic = 0; ic < IC; ++ic) {
#pragma unroll
        for (int ky = 0; ky < 5; ++ky) {
            const float4* rowp =
                reinterpret_cast<const float4*>(&tile[ic][ty + ky][4 * tx]);
            const float4 a0 = rowp[0];
            const float4 a1 = rowp[1];
            const float4 a2 = rowp[2];
            const float v[12] = {a0.x, a0.y, a0.z, a0.w,
                                 a1.x, a1.y, a1.z, a1.w,
                                 a2.x, a2.y, a2.z, a2.w};
            u64 d[8];
#pragma unroll
            for (int j = 0; j < 8; ++j) d[j] = pk(v[2 + j], v[2 + j]);
#pragma unroll
            for (int kx = 0; kx < 5; ++kx) {
                const ulonglong2 wp = wsh2[ic][ky][kx];
#pragma unroll
                for (int p = 0; p < 4; ++p) {
                    acc01[p] = fma2(d[p + kx], wp.x, acc01[p]);
                    acc23[p] = fma2(d[p + kx], wp.y, acc23[p]);
                }
            }
        }
    }

    float o[4][4];   // [oc][px]
#pragma unroll
    for (int p = 0; p < 4; ++p) {
        upk(acc01[p], o[0][p], o[1][p]);
        upk(acc23[p], o[2][p], o[3][p]);
    }

    if (NHWC_OUT) {
        float4* o4 = g_th + (size_t)n * HH * WW + y * WW + xb;
#pragma unroll
        for (int p = 0; p < 4; ++p)
            o4[p] = make_float4(o[0][p], o[1][p], o[2][p], o[3][p]);
    } else {
        // padded CHW out, OC=4 planes -> batch stride 4*PS
        float4* outp = ((DST == 1) ? g_t1p : g_t2p) + (size_t)n * 4 * PS;
        const int fx = (x0 >> 2) + tx + 1;
#pragma unroll
        for (int oc = 0; oc < 4; ++oc)
            outp[(size_t)oc * PS + (y + 2) * PC + fx] =
                make_float4(o[oc][0], o[oc][1], o[oc][2], o[oc][3]);
    }
}

// ---------------------------------------------------------------------------
// Fused: grid build + bilinear grid_sample + stride-3 3x3 conv epilogue.
// theta in NHWC float4 (g_th). x in NHWC float4 (g_xt). Corner cache: the 9
// subsamples perturb the sample point by <<1 px -> refetch only on index change.
// ---------------------------------------------------------------------------
__device__ __forceinline__ float4 fetch4(const float4* __restrict__ b, int x, int y) {
    if ((unsigned)x < (unsigned)WW && (unsigned)y < (unsigned)HH)
        return __ldg(&b[y * WW + x]);
    return make_float4(0.f, 0.f, 0.f, 0.f);
}

__global__ void __launch_bounds__(256) stn_sample_kernel(
    const float* __restrict__ wr, const float* __restrict__ br,
    float* __restrict__ out)
{
    __shared__ float wsh[81];
    __shared__ float bsh[3];
    __shared__ float so[3][32][9];

    const int tx  = threadIdx.x;
    const int ty  = threadIdx.y;
    const int tid = ty * 32 + tx;
    if (tid < 81) wsh[tid] = __ldg(&wr[tid]);
    if (tid < 3)  bsh[tid] = __ldg(&br[tid]);
    __syncthreads();

    const int h0 = blockIdx.x * 32;
    const int w0 = blockIdx.y * 8;
    const int n  = blockIdx.z;
    const int h  = h0 + tx;
    const int w  = w0 + ty;

    const float4* tb = g_th + (size_t)n * HH * WW;
    const float4* xb = g_xt + (size_t)n * HH * WW;

    const float4 th = __ldg(&tb[h * WW + w]);

    const float yy = -1.f + 2.f * (float)h / (float)(HH - 1);
    const float xx = -1.f + 2.f * (float)w / (float)(WW - 1);

    float acc0 = 0.f, acc1 = 0.f, acc2 = 0.f;

    int cxi = (int)0x80000000, cyi = (int)0x80000000;
    float4 c00, c10, c01, c11;
    c00 = c10 = c01 = c11 = make_float4(0.f, 0.f, 0.f, 0.f);

#pragma unroll
    for (int i = 0; i < 3; ++i) {
        const float lyv = (float)(i - 1) * (3.0f / (float)HH);
#pragma unroll
        for (int j = 0; j < 3; ++j) {
            const float lxv = (float)(j - 1) * (3.0f / (float)WW);
            const float gx = yy + th.x * lyv + th.y * lxv;   // grid[...,0] (x coord)
            const float gy = xx + th.z * lyv + th.w * lxv;   // grid[...,1] (y coord)
            const float ix = ((gx + 1.0f) * (float)WW - 1.0f) * 0.5f;
            const float iy = ((gy + 1.0f) * (float)HH - 1.0f) * 0.5f;
            const float ix0 = floorf(ix);
            const float iy0 = floorf(iy);
            const float wx1 = ix - ix0;
            const float wy1 = iy - iy0;
            const float wx0 = 1.0f - wx1;
            const float wy0 = 1.0f - wy1;
            const int xi = (int)ix0;
            const int yi = (int)iy0;

            if (xi != cxi || yi != cyi) {
                c00 = fetch4(xb, xi,     yi);
                c10 = fetch4(xb, xi + 1, yi);
                c01 = fetch4(xb, xi,     yi + 1);
                c11 = fetch4(xb, xi + 1, yi + 1);
                cxi = xi; cyi = yi;
            }

            const float w00 = wx0 * wy0, w10 = wx1 * wy0;
            const float w01 = wx0 * wy1, w11 = wx1 * wy1;

            const float vx = c00.x * w00 + c10.x * w10 + c01.x * w01 + c11.x * w11;
            const float vy = c00.y * w00 + c10.y * w10 + c01.y * w01 + c11.y * w11;
            const float vz = c00.z * w00 + c10.z * w10 + c01.z * w01 + c11.z * w11;

            const int k = i * 3 + j;
            acc0 += wsh[0 * 27 + k] * vx + wsh[0 * 27 + 9 + k] * vy + wsh[0 * 27 + 18 + k] * vz;
            acc1 += wsh[1 * 27 + k] * vx + wsh[1 * 27 + 9 + k] * vy + wsh[1 * 27 + 18 + k] * vz;
            acc2 += wsh[2 * 27 + k] * vx + wsh[2 * 27 + 9 + k] * vy + wsh[2 * 27 + 18 + k] * vz;
        }
    }

    so[0][tx][ty] = acc0 + bsh[0];
    so[1][tx][ty] = acc1 + bsh[1];
    so[2][tx][ty] = acc2 + bsh[2];
    __syncthreads();

    for (int e = tid; e < 3 * 32 * 8; e += 256) {
        int oc = e >> 8;
        int r  = (e >> 3) & 31;
        int c  = e & 7;
        out[((size_t)(n * 3 + oc) * HH + h0 + r) * WW + w0 + c] = so[oc][r][c];
    }
}

// ---------------------------------------------------------------------------
extern "C" void kernel_launch(void* const* d_in, const int* in_sizes, int n_in,
                              void* d_out, int out_size)
{
    const float* x  = (const float*)d_in[0];
    const float* w1 = (const float*)d_in[1];
    const float* b1 = (const float*)d_in[2];
    const float* w2 = (const float*)d_in[3];
    const float* b2 = (const float*)d_in[4];
    const float* w3 = (const float*)d_in[5];
    const float* b3 = (const float*)d_in[6];
    const float* w4 = (const float*)d_in[7];
    const float* b4 = (const float*)d_in[8];
    const float* wr = (const float*)d_in[9];
    const float* br = (const float*)d_in[10];
    float* out = (float*)d_out;

    const dim3 cb(32, 8);
    const dim3 cg(WW / 128, HH / 8, NN);     // (5, 60, 4)

    conv5_kernel<3, 0, 1, false><<<cg, cb>>>(x, w1, b1);        // x -> t1p (+ g_xt pack)
    conv5_kernel<4, 1, 2, false><<<cg, cb>>>(nullptr, w2, b2);  // t1p -> t2p
    conv5_kernel<4, 2, 1, false><<<cg, cb>>>(nullptr, w3, b3);  // t2p -> t1p
    conv5_kernel<4, 1, 2, true ><<<cg, cb>>>(nullptr, w4, b4);  // t1p -> g_th

    const dim3 sb(32, 8);
    const dim3 sg(HH / 32, WW / 8, NN);      // (15, 80, 4)
    stn_sample_kernel<<<sg, sb>>>(wr, br, out);
}